// round 13
// baseline (speedup 1.0000x reference)
#include <cuda_runtime.h>

// VecInt: scaling-and-squaring integration of a stationary velocity field.
// loc_shift [B=2, D=160, H=192, W=160, C=3] float32 (channels = dz,dy,dx).
//   disp = vel / 2^7;  repeat 7x:  disp = disp + warp(disp, disp)
// warp = trilinear sample of disp at (grid + disp), coords clipped to extent.
//
// Model locked by R3/R6/R9: L1tex cost ~ bytes swept per gather LDG. Fix:
// stage tile+halo into STATIC shared memory (41,472 B, no opt-in, no
// cudaFuncSetAttribute, no statics -- harness-safe), gather via LDS.
// H=2 halo covers all steps (P(|d|>=2) ~ 6e-5 at step 7); rare misses take
// an exact global fallback, so correctness never depends on the halo bound.

#define DB 2
#define DD 160
#define DH 192
#define DW 160
#define VOX (DD * DH * DW)        // 4,915,200
#define TOT (DB * VOX)            // 9,830,400

#define TX 32
#define TY 8
#define TZ 4
#define NTHREADS (TX * TY)        // 256
#define HALO 2
#define RX (TX + 2 * HALO)        // 36
#define RY (TY + 2 * HALO)        // 12
#define RZ (TZ + 2 * HALO)        // 8
#define RTOT (RX * RY * RZ)       // 3456

// Hybrid-SoA ping-pong scratch (no cudaMalloc -> __device__ globals), ~236 MB.
__device__ float2 g_zy[2][TOT];   // (dz, dy) per voxel
__device__ float  g_xx[2][TOT];   // dx per voxel

// One warp-and-add step, smem-staged:
//   self   = scale * src[v]
//   pos    = grid(v) + self               (clipped to [0, dim-1])
//   dst[v] = self + scale * trilinear(src, pos)
// IN_PACKED : stage/fallback from packed fp32 harness input (step 1)
// OUT_PACKED: write packed fp32 harness output (step 7)
template <bool IN_PACKED, bool OUT_PACKED>
__global__ void __launch_bounds__(NTHREADS)
vecint_smem(const float* __restrict__ inP, float* __restrict__ outP,
            int in_sel, int out_sel, float scale)
{
    __shared__ float2 szy[RTOT];   // raw (dz, dy)
    __shared__ float  sxx[RTOT];   // raw dx

    const float2* __restrict__ izy = g_zy[in_sel];
    const float*  __restrict__ ixx = g_xx[in_sel];

    const int tIdx = threadIdx.y * TX + threadIdx.x;
    const int tx0  = blockIdx.x * TX;
    const int ty0  = blockIdx.y * TY;
    const int bz   = blockIdx.z;                 // 0 .. DB*(DD/TZ)-1
    const int b    = bz / (DD / TZ);
    const int tz0  = (bz % (DD / TZ)) * TZ;
    const int base = b * VOX;
    const int ox = tx0 - HALO, oy = ty0 - HALO, oz = tz0 - HALO;

    // --- stage region (tile + halo), edge-clamped, raw (unscaled) values ---
    for (int r = tIdx; r < RTOT; r += NTHREADS) {
        const int rz  = r / (RX * RY);
        const int rem = r - rz * (RX * RY);
        const int ry  = rem / RX;
        const int rx  = rem - ry * RX;
        const int gx = min(max(ox + rx, 0), DW - 1);
        const int gy = min(max(oy + ry, 0), DH - 1);
        const int gz = min(max(oz + rz, 0), DD - 1);
        const int gi = base + (gz * DH + gy) * DW + gx;
        if (IN_PACKED) {
            const int p = gi * 3;
            szy[r] = make_float2(__ldg(inP + p + 0), __ldg(inP + p + 1));
            sxx[r] = __ldg(inP + p + 2);
        } else {
            szy[r] = __ldg(izy + gi);
            sxx[r] = __ldg(ixx + gi);
        }
    }
    __syncthreads();

    const int x = tx0 + threadIdx.x;
    const int y = ty0 + threadIdx.y;

    #pragma unroll
    for (int zi = 0; zi < TZ; zi++) {
        const int z = tz0 + zi;

        // self displacement from smem (raw), then scale
        const int ls = (((z - oz) * RY) + (y - oy)) * RX + (x - ox);
        const float2 sv = szy[ls];
        const float d0 = sv.x * scale;
        const float d1 = sv.y * scale;
        const float d2 = sxx[ls] * scale;

        float pz = fminf(fmaxf((float)z + d0, 0.0f), (float)(DD - 1));
        float py = fminf(fmaxf((float)y + d1, 0.0f), (float)(DH - 1));
        float px = fminf(fmaxf((float)x + d2, 0.0f), (float)(DW - 1));

        const float fz0 = floorf(pz), fy0 = floorf(py), fx0 = floorf(px);
        const int z0 = (int)fz0, y0 = (int)fy0, x0 = (int)fx0;
        const int z1 = min(z0 + 1, DD - 1);
        const int y1 = min(y0 + 1, DH - 1);
        const int x1 = min(x0 + 1, DW - 1);

        const float dz = pz - fz0, dy = py - fy0, dx = px - fx0;
        const float wz = 1.0f - dz, wy = 1.0f - dy, wx = 1.0f - dx;

        const float w000 = wz * wy * wx, w001 = wz * wy * dx;
        const float w010 = wz * dy * wx, w011 = wz * dy * dx;
        const float w100 = dz * wy * wx, w101 = dz * wy * dx;
        const float w110 = dz * dy * wx, w111 = dz * dy * dx;

        const int lx0 = x0 - ox, lx1 = x1 - ox;
        const int ly0 = y0 - oy, ly1 = y1 - oy;
        const int lz0 = z0 - oz, lz1 = z1 - oz;

        const bool ok = (lx0 >= 0) & (ly0 >= 0) & (lz0 >= 0) &
                        (lx1 < RX) & (ly1 < RY) & (lz1 < RZ);

        float a0 = 0.0f, a1 = 0.0f, a2 = 0.0f;

        if (ok) {
            const int l00 = (lz0 * RY + ly0) * RX;
            const int l01 = (lz0 * RY + ly1) * RX;
            const int l10 = (lz1 * RY + ly0) * RX;
            const int l11 = (lz1 * RY + ly1) * RX;
            #define SFETCH(L, W)                              \
                do {                                           \
                    const int _l = (L);                        \
                    const float2 _c = szy[_l];                 \
                    const float  _f = sxx[_l];                 \
                    a0 = fmaf((W), _c.x, a0);                  \
                    a1 = fmaf((W), _c.y, a1);                  \
                    a2 = fmaf((W), _f,   a2);                  \
                } while (0)
            SFETCH(l00 + lx0, w000); SFETCH(l00 + lx1, w001);
            SFETCH(l01 + lx0, w010); SFETCH(l01 + lx1, w011);
            SFETCH(l10 + lx0, w100); SFETCH(l10 + lx1, w101);
            SFETCH(l11 + lx0, w110); SFETCH(l11 + lx1, w111);
            #undef SFETCH
        } else {
            // exact global fallback (rare: sample left the staged region)
            const int i00 = base + (z0 * DH + y0) * DW;
            const int i01 = base + (z0 * DH + y1) * DW;
            const int i10 = base + (z1 * DH + y0) * DW;
            const int i11 = base + (z1 * DH + y1) * DW;
            #define GFETCH(IDX, W)                              \
                do {                                             \
                    const int _i = (IDX);                        \
                    if (IN_PACKED) {                             \
                        const int _p = _i * 3;                   \
                        a0 = fmaf((W), __ldg(inP + _p + 0), a0); \
                        a1 = fmaf((W), __ldg(inP + _p + 1), a1); \
                        a2 = fmaf((W), __ldg(inP + _p + 2), a2); \
                    } else {                                     \
                        const float2 _c = __ldg(izy + _i);       \
                        const float  _f = __ldg(ixx + _i);       \
                        a0 = fmaf((W), _c.x, a0);                \
                        a1 = fmaf((W), _c.y, a1);                \
                        a2 = fmaf((W), _f,   a2);                \
                    }                                            \
                } while (0)
            GFETCH(i00 + x0, w000); GFETCH(i00 + x1, w001);
            GFETCH(i01 + x0, w010); GFETCH(i01 + x1, w011);
            GFETCH(i10 + x0, w100); GFETCH(i10 + x1, w101);
            GFETCH(i11 + x0, w110); GFETCH(i11 + x1, w111);
            #undef GFETCH
        }

        const float o0 = fmaf(scale, a0, d0);
        const float o1 = fmaf(scale, a1, d1);
        const float o2 = fmaf(scale, a2, d2);

        const int gi = base + (z * DH + y) * DW + x;
        if (OUT_PACKED) {
            const int p = gi * 3;
            outP[p + 0] = o0;
            outP[p + 1] = o1;
            outP[p + 2] = o2;
        } else {
            g_zy[out_sel][gi] = make_float2(o0, o1);
            g_xx[out_sel][gi] = o2;
        }
    }
}

extern "C" void kernel_launch(void* const* d_in, const int* in_sizes, int n_in,
                              void* d_out, int out_size)
{
    const float* in  = (const float*)d_in[0];
    float*       out = (float*)d_out;

    const float inv = 1.0f / 128.0f;      // 2^-INT_STEPS (INT_STEPS = 7)

    const dim3 blk(TX, TY, 1);                           // 256 threads
    const dim3 grd(DW / TX, DH / TY, DB * (DD / TZ));    // 5 x 24 x 80

    // step 1 (scaling fused): packed input -> planes[0]
    vecint_smem<true,  false><<<grd, blk>>>(in, nullptr, 0, 0, inv);
    // steps 2..6: ping-pong 0->1->0->1->0->1
    vecint_smem<false, false><<<grd, blk>>>(nullptr, nullptr, 0, 1, 1.0f);
    vecint_smem<false, false><<<grd, blk>>>(nullptr, nullptr, 1, 0, 1.0f);
    vecint_smem<false, false><<<grd, blk>>>(nullptr, nullptr, 0, 1, 1.0f);
    vecint_smem<false, false><<<grd, blk>>>(nullptr, nullptr, 1, 0, 1.0f);
    vecint_smem<false, false><<<grd, blk>>>(nullptr, nullptr, 0, 1, 1.0f);
    // step 7: planes[1] -> packed output
    vecint_smem<false, true ><<<grd, blk>>>(nullptr, out, 1, 0, 1.0f);
}

// round 17
// speedup vs baseline: 1.2577x; 1.2577x over previous
#include <cuda_runtime.h>
#include <cuda_fp16.h>

// VecInt: scaling-and-squaring integration of a stationary velocity field.
// loc_shift [B=2, D=160, H=192, W=160, C=3] float32 (channels = dz,dy,dx).
//   disp = vel / 2^7;  repeat 7x:  disp = disp + warp(disp, disp)
// warp = trilinear sample of disp at (grid + disp), coords clipped to extent.
//
// Model locked R3/R6/R9/R13: l1tex wavefront-bound; per-corner cost ~ lines
// touched (any fp32 layout ~8-9 cyc/corner -> 91 us/step floor). Only lever:
// 8-byte fp16x4 gather records (3 lines/corner ~5.1 cyc). Precision is safe
// because sample POSITIONS come from the exact fp32 self path; fp16 only
// perturbs gathered values (~0.75e-4 rel/step, ~4.5e-4 total vs 1e-3 gate).
// R8's 0.171 failure was a ping-pong off-by-one (step 7 read the step-5
// field), fixed here: step 7 reads h[1].

#define DB 2
#define DD 160
#define DH 192
#define DW 160
#define VOX (DD * DH * DW)        // 4,915,200
#define TOT (DB * VOX)            // 9,830,400
#define NTHREADS 256

// Scratch (no cudaMalloc -> __device__ globals):
//   fp32 accumulator planes (in place; each thread touches only its own idx)
//   fp16 packed gather planes (ping-pong): {half2(dz,dy), half2(dx,0)}
__device__ float g_acc[3][TOT];    // ~118 MB
__device__ uint2 g_h[2][TOT];      // ~157 MB

static __device__ __forceinline__ unsigned h2u(__half2 h) {
    return *reinterpret_cast<unsigned*>(&h);
}
static __device__ __forceinline__ __half2 u2h(unsigned u) {
    return *reinterpret_cast<__half2*>(&u);
}

// One warp-and-add step:
//   self   = scale * src[v]          (fp32 exact chain)
//   pos    = grid(v) + self          (clipped to [0, dim-1])  -- fp32 exact
//   dst[v] = self + scale * trilinear(src_fp16, pos)
// IN_PACKED : step 1 -> self+gather from packed fp32 harness input
// OUT_PACKED: step 7 -> write packed fp32 harness output (no plane stores)
template <bool IN_PACKED, bool OUT_PACKED>
__global__ void __launch_bounds__(NTHREADS)
vecint_step(const float* __restrict__ inP, float* __restrict__ outP,
            int in_sel, int out_sel, float scale)
{
    const int tid = blockIdx.x * NTHREADS + threadIdx.x;  // grid exact multiple
    const int x  = tid % DW;
    const int t1 = tid / DW;
    const int y  = t1 % DH;
    const int t2 = t1 / DH;
    const int z  = t2 % DD;
    const int b  = t2 / DD;
    const int base = b * VOX;

    const uint2* __restrict__ hIn = g_h[in_sel];

    // --- own displacement (d0=dz, d1=dy, d2=dx), fp32 chain, pre-scaled ---
    float d0, d1, d2;
    if (IN_PACKED) {
        const int p = tid * 3;
        d0 = __ldg(inP + p + 0);
        d1 = __ldg(inP + p + 1);
        d2 = __ldg(inP + p + 2);
    } else {
        d0 = g_acc[0][tid];
        d1 = g_acc[1][tid];
        d2 = g_acc[2][tid];
    }
    d0 *= scale; d1 *= scale; d2 *= scale;

    // --- sample coords, clipped exactly like reference (clip -> floor) ---
    float pz = fminf(fmaxf((float)z + d0, 0.0f), (float)(DD - 1));
    float py = fminf(fmaxf((float)y + d1, 0.0f), (float)(DH - 1));
    float px = fminf(fmaxf((float)x + d2, 0.0f), (float)(DW - 1));

    const float fz0 = floorf(pz), fy0 = floorf(py), fx0 = floorf(px);
    const int z0 = (int)fz0, y0 = (int)fy0, x0 = (int)fx0;
    const int z1 = min(z0 + 1, DD - 1);
    const int y1 = min(y0 + 1, DH - 1);
    const int x1 = min(x0 + 1, DW - 1);

    const float dz = pz - fz0, dy = py - fy0, dx = px - fx0;
    const float wz = 1.0f - dz, wy = 1.0f - dy, wx = 1.0f - dx;

    const float w000 = wz * wy * wx, w001 = wz * wy * dx;
    const float w010 = wz * dy * wx, w011 = wz * dy * dx;
    const float w100 = dz * wy * wx, w101 = dz * wy * dx;
    const float w110 = dz * dy * wx, w111 = dz * dy * dx;

    const int i00 = base + (z0 * DH + y0) * DW;
    const int i01 = base + (z0 * DH + y1) * DW;
    const int i10 = base + (z1 * DH + y0) * DW;
    const int i11 = base + (z1 * DH + y1) * DW;

    float a0 = 0.0f, a1 = 0.0f, a2 = 0.0f;

    #define FETCH(IDX, W)                                            \
        do {                                                          \
            const int _i = (IDX);                                     \
            if (IN_PACKED) {                                          \
                const int _p = _i * 3;                                \
                a0 = fmaf((W), __ldg(inP + _p + 0), a0);              \
                a1 = fmaf((W), __ldg(inP + _p + 1), a1);              \
                a2 = fmaf((W), __ldg(inP + _p + 2), a2);              \
            } else {                                                  \
                const uint2 _u = __ldg(hIn + _i);                     \
                const float2 _zy = __half22float2(u2h(_u.x));         \
                const float  _xx = __low2float(u2h(_u.y));            \
                a0 = fmaf((W), _zy.x, a0);                            \
                a1 = fmaf((W), _zy.y, a1);                            \
                a2 = fmaf((W), _xx,   a2);                            \
            }                                                         \
        } while (0)

    FETCH(i00 + x0, w000);
    FETCH(i00 + x1, w001);
    FETCH(i01 + x0, w010);
    FETCH(i01 + x1, w011);
    FETCH(i10 + x0, w100);
    FETCH(i10 + x1, w101);
    FETCH(i11 + x0, w110);
    FETCH(i11 + x1, w111);
    #undef FETCH

    const float o0 = fmaf(scale, a0, d0);
    const float o1 = fmaf(scale, a1, d1);
    const float o2 = fmaf(scale, a2, d2);

    if (OUT_PACKED) {
        const int p = tid * 3;
        outP[p + 0] = o0;
        outP[p + 1] = o1;
        outP[p + 2] = o2;
    } else {
        // fp32 accumulator (in place; only this thread touches index tid)
        g_acc[0][tid] = o0;
        g_acc[1][tid] = o1;
        g_acc[2][tid] = o2;
        // fp16 packed gather plane (ping-pong)
        uint2 u;
        u.x = h2u(__floats2half2_rn(o0, o1));
        u.y = h2u(__floats2half2_rn(o2, 0.0f));
        g_h[out_sel][tid] = u;
    }
}

extern "C" void kernel_launch(void* const* d_in, const int* in_sizes, int n_in,
                              void* d_out, int out_size)
{
    const float* in  = (const float*)d_in[0];
    float*       out = (float*)d_out;

    const int nblocks = TOT / NTHREADS;   // 38,400 exactly
    const float inv = 1.0f / 128.0f;      // 2^-INT_STEPS (INT_STEPS = 7)

    // step 1 (scaling fused): packed fp32 input -> acc (=o1) + h[0] (=fp16 o1)
    vecint_step<true,  false><<<nblocks, NTHREADS>>>(in, nullptr, 0, 0, inv);
    // steps 2..6: self from fp32 acc (in place), gathers from fp16 ping-pong
    // L2: h[0]->h[1]  L3: h[1]->h[0]  L4: h[0]->h[1]  L5: h[1]->h[0]  L6: h[0]->h[1]
    vecint_step<false, false><<<nblocks, NTHREADS>>>(nullptr, nullptr, 0, 1, 1.0f);
    vecint_step<false, false><<<nblocks, NTHREADS>>>(nullptr, nullptr, 1, 0, 1.0f);
    vecint_step<false, false><<<nblocks, NTHREADS>>>(nullptr, nullptr, 0, 1, 1.0f);
    vecint_step<false, false><<<nblocks, NTHREADS>>>(nullptr, nullptr, 1, 0, 1.0f);
    vecint_step<false, false><<<nblocks, NTHREADS>>>(nullptr, nullptr, 0, 1, 1.0f);
    // step 7: gathers from h[1] (=o6), self from acc (=o6) -> packed output
    vecint_step<false, true ><<<nblocks, NTHREADS>>>(nullptr, out, 1, 0, 1.0f);
}